// round 7
// baseline (speedup 1.0000x reference)
#include <cuda_runtime.h>
#include <cuda_bf16.h>
#include <math.h>

#define NUM_SEG 16
#define CHAN 128
#define HID 32

// Pass-1: 128 thr (4 warps), ~33KB smem -> 6 blocks/SM. Single full wave.
#define NBLK1 888          // 148 SMs * 6 blocks
#define THR1 128

// Modulate: 256 thr, <=64 regs -> 4 blocks/SM. Single full wave.
#define NBLK3 592          // 148 * 4
#define THR3 256

__device__ float g_part[(size_t)NBLK1 * NUM_SEG * CHAN];  // per-block partial sums
__device__ float g_cntp[NBLK1 * NUM_SEG];                 // per-block partial counts
__device__ float g_gate[NUM_SEG * CHAN];                  // final gates

// ---- packed f32x2 helpers (sm_103a) --------------------------------------
__device__ __forceinline__ unsigned long long fadd2(unsigned long long a,
                                                    unsigned long long b) {
    unsigned long long r;
    asm("add.rn.f32x2 %0, %1, %2;" : "=l"(r) : "l"(a), "l"(b));
    return r;
}
__device__ __forceinline__ unsigned long long fmul2(unsigned long long a,
                                                    unsigned long long b) {
    unsigned long long r;
    asm("mul.rn.f32x2 %0, %1, %2;" : "=l"(r) : "l"(a), "l"(b));
    return r;
}

struct F4 { unsigned long long lo, hi; };  // float4 as 2x f32x2

__device__ __forceinline__ F4 ld_f4_cs(const F4* p) {
    F4 r;
    asm("ld.global.cs.v4.b32 {%0,%1,%2,%3}, [%4];"
        : "=r"(((unsigned*)&r)[0]), "=r"(((unsigned*)&r)[1]),
          "=r"(((unsigned*)&r)[2]), "=r"(((unsigned*)&r)[3])
        : "l"(p));
    return r;
}
__device__ __forceinline__ void st_f4_cs(F4* p, F4 v) {
    asm volatile("st.global.cs.v4.b32 [%0], {%1,%2,%3,%4};"
        :: "l"(p),
           "r"(((unsigned*)&v)[0]), "r"(((unsigned*)&v)[1]),
           "r"(((unsigned*)&v)[2]), "r"(((unsigned*)&v)[3]));
}

__device__ __forceinline__ void rmw(F4* buf, int s, int lane, F4 v) {
    F4* p = buf + s * 32 + lane;
    F4 a = *p;
    a.lo = fadd2(a.lo, v.lo);
    a.hi = fadd2(a.hi, v.hi);
    *p = a;
}

// ---------------------------------------------------------------------------
// Kernel 1: segment sums. Warp owns full rows (float4/lane), 8KB private smem
// region per warp, non-atomic RMW. 8 rows/iter, indices via two uniform int4
// LDGs, x-loads batched. (R4 form: at its LSU-issue floor ~12.5 cyc/row.)
// ---------------------------------------------------------------------------
__global__ void __launch_bounds__(THR1) seg_sum_kernel(
    const float* __restrict__ x, const int* __restrict__ idx, int N)
{
    __shared__ F4 s_acc[4 * NUM_SEG * 32];   // 32KB
    __shared__ float s_cnt[4 * NUM_SEG];

    const int tid  = threadIdx.x;
    const int lane = tid & 31;
    const int w    = tid >> 5;

    F4* buf = s_acc + w * (NUM_SEG * 32);

    for (int i = tid; i < 4 * NUM_SEG * 32; i += THR1) {
        s_acc[i].lo = 0ull; s_acc[i].hi = 0ull;
    }
    __syncthreads();

    const int gw = blockIdx.x * 4 + w;   // global warp id
    const int NW = NBLK1 * 4;            // total warps
    const F4* X = (const F4*)x;
    const int ngroups = N >> 3;          // groups of 8 rows

    int cnt = 0;
    for (int g = gw; g < ngroups; g += NW) {
        const int base = g << 3;
        int4 i0 = __ldg((const int4*)(idx + base));
        int4 i1 = __ldg((const int4*)(idx + base + 4));
        const size_t o = (size_t)base * 32 + lane;
        F4 v0 = ld_f4_cs(X + o);
        F4 v1 = ld_f4_cs(X + o + 32);
        F4 v2 = ld_f4_cs(X + o + 64);
        F4 v3 = ld_f4_cs(X + o + 96);
        F4 v4 = ld_f4_cs(X + o + 128);
        F4 v5 = ld_f4_cs(X + o + 160);
        F4 v6 = ld_f4_cs(X + o + 192);
        F4 v7 = ld_f4_cs(X + o + 224);

        cnt += (i0.x == lane) + (i0.y == lane) + (i0.z == lane) + (i0.w == lane)
             + (i1.x == lane) + (i1.y == lane) + (i1.z == lane) + (i1.w == lane);

        rmw(buf, i0.x, lane, v0);
        rmw(buf, i0.y, lane, v1);
        rmw(buf, i0.z, lane, v2);
        rmw(buf, i0.w, lane, v3);
        rmw(buf, i1.x, lane, v4);
        rmw(buf, i1.y, lane, v5);
        rmw(buf, i1.z, lane, v6);
        rmw(buf, i1.w, lane, v7);
    }
    // tail (N not multiple of 8)
    for (int r = (ngroups << 3) + gw; r < N; r += NW) {
        int s = __ldg(idx + r);
        F4 v = ld_f4_cs(X + (size_t)r * 32 + lane);
        cnt += (s == lane);
        rmw(buf, s, lane, v);
    }

    if (lane < NUM_SEG) s_cnt[w * NUM_SEG + lane] = (float)cnt;
    __syncthreads();

    // Combine 4 warp regions -> per-block partials in GMEM (u64 view).
    const unsigned long long* sa = (const unsigned long long*)s_acc;
    const int R = NUM_SEG * 64;  // u64 elements per region (1024)
    for (int i = tid; i < R; i += THR1) {
        unsigned long long v = sa[i];
        v = fadd2(v, sa[R + i]);
        v = fadd2(v, sa[2 * R + i]);
        v = fadd2(v, sa[3 * R + i]);
        ((unsigned long long*)g_part)[(size_t)blockIdx.x * R + i] = v;
    }
    if (tid < NUM_SEG) {
        g_cntp[blockIdx.x * NUM_SEG + tid] =
            s_cnt[tid] + s_cnt[NUM_SEG + tid] +
            s_cnt[2 * NUM_SEG + tid] + s_cnt[3 * NUM_SEG + tid];
    }
}

// ---------------------------------------------------------------------------
// Kernel 2: reduce partials + SE MLP. Grid = 16 blocks, 1024 threads.
// ---------------------------------------------------------------------------
__global__ void __launch_bounds__(1024) reduce_mlp_kernel(
    const float* __restrict__ W1, const float* __restrict__ W2)
{
    const int s    = blockIdx.x;
    const int tid  = threadIdx.x;
    const int c    = tid & (CHAN - 1);
    const int part = tid >> 7;  // 0..7

    __shared__ float red[1024];
    __shared__ float s_pooled[CHAN];
    __shared__ float s_h[HID];

    // counts
    float cacc = 0.f;
    for (int b = tid; b < NBLK1; b += 1024)
        cacc += g_cntp[b * NUM_SEG + s];
    red[tid] = cacc;
    __syncthreads();
    #pragma unroll
    for (int off = 512; off > 0; off >>= 1) {
        if (tid < off) red[tid] += red[tid + off];
        __syncthreads();
    }
    float cnt = fmaxf(red[0], 1.0f);
    __syncthreads();

    // sums: 8 threads per channel split the block range
    float sum = 0.f;
    #pragma unroll 8
    for (int b = part; b < NBLK1; b += 8)
        sum += g_part[(size_t)b * (NUM_SEG * CHAN) + s * CHAN + c];
    red[tid] = sum;
    __syncthreads();
    if (tid < CHAN) {
        float v = 0.f;
        #pragma unroll
        for (int p = 0; p < 8; p++) v += red[p * 128 + tid];
        s_pooled[tid] = v / cnt;
    }
    __syncthreads();

    if (tid < HID) {
        float acc = 0.f;
        #pragma unroll 8
        for (int k = 0; k < CHAN; k++)
            acc += s_pooled[k] * __ldg(W1 + tid * CHAN + k);
        s_h[tid] = fmaxf(acc, 0.f);
    }
    __syncthreads();

    if (tid < CHAN) {
        float acc = 0.f;
        #pragma unroll
        for (int k = 0; k < HID; k++)
            acc += s_h[k] * __ldg(W2 + tid * HID + k);
        g_gate[s * CHAN + tid] = 1.0f / (1.0f + expf(-acc));
    }
}

// ---------------------------------------------------------------------------
// Kernel 3: out = x * gate[idx]. Warp owns 4 consecutive rows per iteration:
// ONE uniform int4 LDG covers all 4 indices (amortizes the per-row idx load
// that previously cost 4 LSU cycles/row), 4 LDG.128 batched in flight,
// then 4 fused f32x2 muls + STG.128. LSU cost ~13 cyc/row < 23-cyc DRAM
// budget -> purely DRAM-bound.
// ---------------------------------------------------------------------------
__global__ void __launch_bounds__(THR3, 4) modulate_kernel(
    const float* __restrict__ x, const int* __restrict__ idx,
    float* __restrict__ out, int N)
{
    __shared__ F4 s_gate[NUM_SEG * 32];  // 8KB

    for (int i = threadIdx.x; i < NUM_SEG * 32; i += THR3)
        s_gate[i] = ((const F4*)g_gate)[i];
    __syncthreads();

    const int lane = threadIdx.x & 31;
    const int w    = threadIdx.x >> 5;
    const int gw   = blockIdx.x * 8 + w;   // global warp id
    const int NW   = NBLK3 * 8;            // total warps

    const F4* X = (const F4*)x;
    F4* O = (F4*)out;
    const int ngroups = N >> 2;            // groups of 4 rows

    for (int g = gw; g < ngroups; g += NW) {
        const int base = g << 2;
        int4 is = __ldg((const int4*)(idx + base));
        const size_t o = (size_t)base * 32 + lane;
        F4 v0 = ld_f4_cs(X + o);
        F4 v1 = ld_f4_cs(X + o + 32);
        F4 v2 = ld_f4_cs(X + o + 64);
        F4 v3 = ld_f4_cs(X + o + 96);

        F4 g0 = s_gate[is.x * 32 + lane];
        F4 g1 = s_gate[is.y * 32 + lane];
        F4 g2 = s_gate[is.z * 32 + lane];
        F4 g3 = s_gate[is.w * 32 + lane];

        v0.lo = fmul2(v0.lo, g0.lo); v0.hi = fmul2(v0.hi, g0.hi);
        v1.lo = fmul2(v1.lo, g1.lo); v1.hi = fmul2(v1.hi, g1.hi);
        v2.lo = fmul2(v2.lo, g2.lo); v2.hi = fmul2(v2.hi, g2.hi);
        v3.lo = fmul2(v3.lo, g3.lo); v3.hi = fmul2(v3.hi, g3.hi);

        st_f4_cs(O + o, v0);
        st_f4_cs(O + o + 32, v1);
        st_f4_cs(O + o + 64, v2);
        st_f4_cs(O + o + 96, v3);
    }
    // tail (N not multiple of 4)
    for (int r = (ngroups << 2) + gw; r < N; r += NW) {
        int s = __ldg(idx + r);
        const size_t o = (size_t)r * 32 + lane;
        F4 v = ld_f4_cs(X + o);
        F4 gt = s_gate[s * 32 + lane];
        v.lo = fmul2(v.lo, gt.lo); v.hi = fmul2(v.hi, gt.hi);
        st_f4_cs(O + o, v);
    }
}

// ---------------------------------------------------------------------------
extern "C" void kernel_launch(void* const* d_in, const int* in_sizes, int n_in,
                              void* d_out, int out_size)
{
    const float* x   = (const float*)d_in[0];
    const int*   idx = (const int*)d_in[1];
    const float* W1  = (const float*)d_in[2];
    const float* W2  = (const float*)d_in[3];
    float* out = (float*)d_out;

    const int N = in_sizes[1];  // number of points

    seg_sum_kernel<<<NBLK1, THR1>>>(x, idx, N);
    reduce_mlp_kernel<<<NUM_SEG, 1024>>>(W1, W2);
    modulate_kernel<<<NBLK3, THR3>>>(x, idx, out, N);
}

// round 8
// speedup vs baseline: 1.0027x; 1.0027x over previous
#include <cuda_runtime.h>
#include <cuda_bf16.h>
#include <math.h>

#define NUM_SEG 16
#define CHAN 128
#define HID 32
#define NPHASE 8

// Pass-1: 128 thr (4 warps), ~33KB smem -> 6 blocks/SM. Single full wave.
#define NBLK1 888          // 148 SMs * 6 blocks
#define THR1 128

// Modulate: R5 form, 8 blocks/SM single wave
#define NBLK3 1184
#define THR3 256

__device__ float g_part[(size_t)NBLK1 * NUM_SEG * CHAN];  // per-block partial sums
__device__ float g_cntp[NBLK1 * NUM_SEG];                 // per-block partial counts
__device__ float g_mid[NPHASE * NUM_SEG * CHAN];          // stage-A partials
__device__ float g_gate[NUM_SEG * CHAN];                  // final gates

// ---- packed f32x2 helpers (sm_103a) --------------------------------------
__device__ __forceinline__ unsigned long long fadd2(unsigned long long a,
                                                    unsigned long long b) {
    unsigned long long r;
    asm("add.rn.f32x2 %0, %1, %2;" : "=l"(r) : "l"(a), "l"(b));
    return r;
}
__device__ __forceinline__ unsigned long long fmul2(unsigned long long a,
                                                    unsigned long long b) {
    unsigned long long r;
    asm("mul.rn.f32x2 %0, %1, %2;" : "=l"(r) : "l"(a), "l"(b));
    return r;
}

struct F4 { unsigned long long lo, hi; };  // float4 as 2x f32x2

__device__ __forceinline__ F4 ld_f4_cs(const F4* p) {
    F4 r;
    asm("ld.global.cs.v4.b32 {%0,%1,%2,%3}, [%4];"
        : "=r"(((unsigned*)&r)[0]), "=r"(((unsigned*)&r)[1]),
          "=r"(((unsigned*)&r)[2]), "=r"(((unsigned*)&r)[3])
        : "l"(p));
    return r;
}

__device__ __forceinline__ void rmw(F4* buf, int s, int lane, F4 v) {
    F4* p = buf + s * 32 + lane;
    F4 a = *p;
    a.lo = fadd2(a.lo, v.lo);
    a.hi = fadd2(a.hi, v.hi);
    *p = a;
}

// ---------------------------------------------------------------------------
// Kernel 1: segment sums (R6 form, at its L1tex/DRAM co-limit ~12 wf/row).
// ---------------------------------------------------------------------------
__global__ void __launch_bounds__(THR1) seg_sum_kernel(
    const float* __restrict__ x, const int* __restrict__ idx, int N)
{
    __shared__ F4 s_acc[4 * NUM_SEG * 32];   // 32KB
    __shared__ float s_cnt[4 * NUM_SEG];

    const int tid  = threadIdx.x;
    const int lane = tid & 31;
    const int w    = tid >> 5;

    F4* buf = s_acc + w * (NUM_SEG * 32);

    for (int i = tid; i < 4 * NUM_SEG * 32; i += THR1) {
        s_acc[i].lo = 0ull; s_acc[i].hi = 0ull;
    }
    __syncthreads();

    const int gw = blockIdx.x * 4 + w;   // global warp id
    const int NW = NBLK1 * 4;            // total warps
    const F4* X = (const F4*)x;
    const int ngroups = N >> 3;          // groups of 8 rows

    int cnt = 0;
    for (int g = gw; g < ngroups; g += NW) {
        const int base = g << 3;
        int4 i0 = __ldg((const int4*)(idx + base));
        int4 i1 = __ldg((const int4*)(idx + base + 4));
        const size_t o = (size_t)base * 32 + lane;
        F4 v0 = ld_f4_cs(X + o);
        F4 v1 = ld_f4_cs(X + o + 32);
        F4 v2 = ld_f4_cs(X + o + 64);
        F4 v3 = ld_f4_cs(X + o + 96);
        F4 v4 = ld_f4_cs(X + o + 128);
        F4 v5 = ld_f4_cs(X + o + 160);
        F4 v6 = ld_f4_cs(X + o + 192);
        F4 v7 = ld_f4_cs(X + o + 224);

        cnt += (i0.x == lane) + (i0.y == lane) + (i0.z == lane) + (i0.w == lane)
             + (i1.x == lane) + (i1.y == lane) + (i1.z == lane) + (i1.w == lane);

        rmw(buf, i0.x, lane, v0);
        rmw(buf, i0.y, lane, v1);
        rmw(buf, i0.z, lane, v2);
        rmw(buf, i0.w, lane, v3);
        rmw(buf, i1.x, lane, v4);
        rmw(buf, i1.y, lane, v5);
        rmw(buf, i1.z, lane, v6);
        rmw(buf, i1.w, lane, v7);
    }
    // tail (N not multiple of 8)
    for (int r = (ngroups << 3) + gw; r < N; r += NW) {
        int s = __ldg(idx + r);
        F4 v = ld_f4_cs(X + (size_t)r * 32 + lane);
        cnt += (s == lane);
        rmw(buf, s, lane, v);
    }

    if (lane < NUM_SEG) s_cnt[w * NUM_SEG + lane] = (float)cnt;
    __syncthreads();

    // Combine 4 warp regions -> per-block partials in GMEM (u64 view).
    const unsigned long long* sa = (const unsigned long long*)s_acc;
    const int R = NUM_SEG * 64;  // u64 elements per region (1024)
    for (int i = tid; i < R; i += THR1) {
        unsigned long long v = sa[i];
        v = fadd2(v, sa[R + i]);
        v = fadd2(v, sa[2 * R + i]);
        v = fadd2(v, sa[3 * R + i]);
        ((unsigned long long*)g_part)[(size_t)blockIdx.x * R + i] = v;
    }
    if (tid < NUM_SEG) {
        g_cntp[blockIdx.x * NUM_SEG + tid] =
            s_cnt[tid] + s_cnt[NUM_SEG + tid] +
            s_cnt[2 * NUM_SEG + tid] + s_cnt[3 * NUM_SEG + tid];
    }
}

// ---------------------------------------------------------------------------
// Kernel 2a: stage-A reduction. 128 blocks = (phase k, segment s).
// Block sums g_part[b][s][:] over b = k, k+8, ... (deterministic fixed order).
// Spreads the 7.3MB partial read over 128 SMs instead of 16.
// ---------------------------------------------------------------------------
__global__ void __launch_bounds__(CHAN) reduce_stageA_kernel()
{
    const int k = blockIdx.x & (NPHASE - 1);
    const int s = blockIdx.x >> 3;
    const int c = threadIdx.x;

    float sum = 0.f;
    #pragma unroll 4
    for (int b = k; b < NBLK1; b += NPHASE)
        sum += g_part[(size_t)b * (NUM_SEG * CHAN) + s * CHAN + c];
    g_mid[(k * NUM_SEG + s) * CHAN + c] = sum;
}

// ---------------------------------------------------------------------------
// Kernel 2b: final reduce + SE MLP. 16 blocks x 128 threads.
// ---------------------------------------------------------------------------
__global__ void __launch_bounds__(CHAN) reduce_mlp_kernel(
    const float* __restrict__ W1, const float* __restrict__ W2)
{
    const int s = blockIdx.x;
    const int c = threadIdx.x;

    __shared__ float s_pooled[CHAN];
    __shared__ float s_h[HID];
    __shared__ float s_red[CHAN];

    // counts (57KB total read, strided)
    float cacc = 0.f;
    for (int b = c; b < NBLK1; b += CHAN)
        cacc += g_cntp[b * NUM_SEG + s];
    s_red[c] = cacc;
    __syncthreads();
    #pragma unroll
    for (int off = CHAN / 2; off > 0; off >>= 1) {
        if (c < off) s_red[c] += s_red[c + off];
        __syncthreads();
    }
    float cnt = fmaxf(s_red[0], 1.0f);

    // sum the 8 stage-A mids (fixed order)
    float sum = 0.f;
    #pragma unroll
    for (int k = 0; k < NPHASE; k++)
        sum += g_mid[(k * NUM_SEG + s) * CHAN + c];
    s_pooled[c] = sum / cnt;
    __syncthreads();

    if (c < HID) {
        float acc = 0.f;
        #pragma unroll 8
        for (int kk = 0; kk < CHAN; kk++)
            acc += s_pooled[kk] * __ldg(W1 + c * CHAN + kk);
        s_h[c] = fmaxf(acc, 0.f);
    }
    __syncthreads();

    float acc = 0.f;
    #pragma unroll
    for (int kk = 0; kk < HID; kk++)
        acc += s_h[kk] * __ldg(W2 + c * HID + kk);
    g_gate[s * CHAN + c] = 1.0f / (1.0f + expf(-acc));
}

// ---------------------------------------------------------------------------
// Kernel 3: out = x * gate[idx]. R5 form (best measured: pure DRAM-bound at
// ~6.1 TB/s mixed R/W). Warp iteration covers 8 rows; LSU ~3 cyc/row.
// ---------------------------------------------------------------------------
__global__ void __launch_bounds__(THR3) modulate_kernel(
    const float* __restrict__ x, const int* __restrict__ idx,
    float* __restrict__ out, int N)
{
    __shared__ float4 s_gate[NUM_SEG * 32];  // 8KB

    for (int i = threadIdx.x; i < NUM_SEG * 32; i += THR3)
        s_gate[i] = ((const float4*)g_gate)[i];
    __syncthreads();

    const float4* X = (const float4*)x;
    float4* O = (float4*)out;
    const int total  = N * 32;
    const int stride = NBLK3 * THR3;

    #pragma unroll 4
    for (int i = blockIdx.x * THR3 + threadIdx.x; i < total; i += stride) {
        int row  = i >> 5;
        int lane = i & 31;
        int s = __ldg(idx + row);
        float4 v = __ldcs(X + i);
        float4 g = s_gate[s * 32 + lane];
        unsigned long long* vp = (unsigned long long*)&v;
        const unsigned long long* gp = (const unsigned long long*)&g;
        vp[0] = fmul2(vp[0], gp[0]);
        vp[1] = fmul2(vp[1], gp[1]);
        __stcs(O + i, v);
    }
}

// ---------------------------------------------------------------------------
extern "C" void kernel_launch(void* const* d_in, const int* in_sizes, int n_in,
                              void* d_out, int out_size)
{
    const float* x   = (const float*)d_in[0];
    const int*   idx = (const int*)d_in[1];
    const float* W1  = (const float*)d_in[2];
    const float* W2  = (const float*)d_in[3];
    float* out = (float*)d_out;

    const int N = in_sizes[1];  // number of points

    seg_sum_kernel<<<NBLK1, THR1>>>(x, idx, N);
    reduce_stageA_kernel<<<NPHASE * NUM_SEG, CHAN>>>();
    reduce_mlp_kernel<<<NUM_SEG, CHAN>>>(W1, W2);
    modulate_kernel<<<NBLK3, THR3>>>(x, idx, out, N);
}

// round 10
// speedup vs baseline: 1.0476x; 1.0448x over previous
#include <cuda_runtime.h>
#include <cuda_bf16.h>
#include <math.h>

#define NUM_SEG 16
#define CHAN 128
#define HID 32

// Pass-1: 128 thr (4 warps), ~33KB smem -> 6 blocks/SM. Single full wave.
#define NBLK1 888          // 148 SMs * 6 blocks
#define THR1 128

// Modulate: 8 blocks/SM single wave
#define NBLK3 1184
#define THR3 256

// Zero-initialized at module load; reduce_mlp re-zeroes after consuming, so
// the zero invariant holds across every graph replay (same work every call).
__device__ float g_sum[NUM_SEG * CHAN];   // atomic accumulators
__device__ float g_cnt[NUM_SEG];          // atomic count accumulators
__device__ float g_gate[NUM_SEG * CHAN];  // final gates

// ---- packed f32x2 helpers (sm_103a) --------------------------------------
__device__ __forceinline__ unsigned long long fadd2(unsigned long long a,
                                                    unsigned long long b) {
    unsigned long long r;
    asm("add.rn.f32x2 %0, %1, %2;" : "=l"(r) : "l"(a), "l"(b));
    return r;
}
__device__ __forceinline__ unsigned long long fmul2(unsigned long long a,
                                                    unsigned long long b) {
    unsigned long long r;
    asm("mul.rn.f32x2 %0, %1, %2;" : "=l"(r) : "l"(a), "l"(b));
    return r;
}

struct F4 { unsigned long long lo, hi; };  // float4 as 2x f32x2

__device__ __forceinline__ F4 ld_f4_cs(const F4* p) {
    F4 r;
    asm("ld.global.cs.v4.b32 {%0,%1,%2,%3}, [%4];"
        : "=r"(((unsigned*)&r)[0]), "=r"(((unsigned*)&r)[1]),
          "=r"(((unsigned*)&r)[2]), "=r"(((unsigned*)&r)[3])
        : "l"(p));
    return r;
}

__device__ __forceinline__ void rmw(F4* buf, int s, int lane, F4 v) {
    F4* p = buf + s * 32 + lane;
    F4 a = *p;
    a.lo = fadd2(a.lo, v.lo);
    a.hi = fadd2(a.hi, v.hi);
    *p = a;
}

// ---------------------------------------------------------------------------
// Kernel 1: segment sums (at its L1tex/DRAM co-limit ~12 wf/row). Epilogue:
// combine the 4 warp-private regions, then RED (atomicAdd, no return) the
// 2048 floats straight into g_sum — no partial buffer round-trip.
// ---------------------------------------------------------------------------
__global__ void __launch_bounds__(THR1) seg_sum_kernel(
    const float* __restrict__ x, const int* __restrict__ idx, int N)
{
    __shared__ F4 s_acc[4 * NUM_SEG * 32];   // 32KB
    __shared__ float s_cnt[4 * NUM_SEG];

    const int tid  = threadIdx.x;
    const int lane = tid & 31;
    const int w    = tid >> 5;

    F4* buf = s_acc + w * (NUM_SEG * 32);

    for (int i = tid; i < 4 * NUM_SEG * 32; i += THR1) {
        s_acc[i].lo = 0ull; s_acc[i].hi = 0ull;
    }
    __syncthreads();

    const int gw = blockIdx.x * 4 + w;   // global warp id
    const int NW = NBLK1 * 4;            // total warps
    const F4* X = (const F4*)x;
    const int ngroups = N >> 3;          // groups of 8 rows

    int cnt = 0;
    for (int g = gw; g < ngroups; g += NW) {
        const int base = g << 3;
        int4 i0 = __ldg((const int4*)(idx + base));
        int4 i1 = __ldg((const int4*)(idx + base + 4));
        const size_t o = (size_t)base * 32 + lane;
        F4 v0 = ld_f4_cs(X + o);
        F4 v1 = ld_f4_cs(X + o + 32);
        F4 v2 = ld_f4_cs(X + o + 64);
        F4 v3 = ld_f4_cs(X + o + 96);
        F4 v4 = ld_f4_cs(X + o + 128);
        F4 v5 = ld_f4_cs(X + o + 160);
        F4 v6 = ld_f4_cs(X + o + 192);
        F4 v7 = ld_f4_cs(X + o + 224);

        cnt += (i0.x == lane) + (i0.y == lane) + (i0.z == lane) + (i0.w == lane)
             + (i1.x == lane) + (i1.y == lane) + (i1.z == lane) + (i1.w == lane);

        rmw(buf, i0.x, lane, v0);
        rmw(buf, i0.y, lane, v1);
        rmw(buf, i0.z, lane, v2);
        rmw(buf, i0.w, lane, v3);
        rmw(buf, i1.x, lane, v4);
        rmw(buf, i1.y, lane, v5);
        rmw(buf, i1.z, lane, v6);
        rmw(buf, i1.w, lane, v7);
    }
    // tail (N not multiple of 8)
    for (int r = (ngroups << 3) + gw; r < N; r += NW) {
        int s = __ldg(idx + r);
        F4 v = ld_f4_cs(X + (size_t)r * 32 + lane);
        cnt += (s == lane);
        rmw(buf, s, lane, v);
    }

    if (lane < NUM_SEG) s_cnt[w * NUM_SEG + lane] = (float)cnt;
    __syncthreads();

    // Combine 4 warp regions -> RED into g_sum. Region float layout is
    // exactly [seg*128 + chan], matching g_sum.
    const float* sa = (const float*)s_acc;
    const int R = NUM_SEG * CHAN;  // 2048 floats per region
    #pragma unroll 4
    for (int i = tid; i < R; i += THR1) {
        float v = sa[i] + sa[R + i] + sa[2 * R + i] + sa[3 * R + i];
        atomicAdd(&g_sum[i], v);
    }
    if (tid < NUM_SEG) {
        float c = s_cnt[tid] + s_cnt[NUM_SEG + tid] +
                  s_cnt[2 * NUM_SEG + tid] + s_cnt[3 * NUM_SEG + tid];
        atomicAdd(&g_cnt[tid], c);
    }
}

// ---------------------------------------------------------------------------
// Kernel 2: SE MLP on the accumulated sums (8KB read), then RE-ZERO the
// accumulators so the next graph replay starts from the zero invariant.
// 16 blocks x 128 threads. All reads of g_sum/g_cnt happen before the
// barrier; re-zero stores happen after it.
// ---------------------------------------------------------------------------
__global__ void __launch_bounds__(CHAN) reduce_mlp_kernel(
    const float* __restrict__ W1, const float* __restrict__ W2)
{
    const int s = blockIdx.x;
    const int c = threadIdx.x;

    __shared__ float s_pooled[CHAN];
    __shared__ float s_h[HID];

    float cnt = fmaxf(g_cnt[s], 1.0f);
    s_pooled[c] = g_sum[s * CHAN + c] / cnt;
    __syncthreads();

    // g_sum/g_cnt fully consumed above -> restore zero invariant now.
    g_sum[s * CHAN + c] = 0.f;
    if (c == 0) g_cnt[s] = 0.f;

    if (c < HID) {
        float acc = 0.f;
        #pragma unroll 8
        for (int k = 0; k < CHAN; k++)
            acc += s_pooled[k] * __ldg(W1 + c * CHAN + k);
        s_h[c] = fmaxf(acc, 0.f);
    }
    __syncthreads();

    float acc = 0.f;
    #pragma unroll
    for (int k = 0; k < HID; k++)
        acc += s_h[k] * __ldg(W2 + c * HID + k);
    g_gate[s * CHAN + c] = 1.0f / (1.0f + expf(-acc));
}

// ---------------------------------------------------------------------------
// Kernel 3: out = x * gate[idx] (measured at the mixed R/W DRAM cap).
// ---------------------------------------------------------------------------
__global__ void __launch_bounds__(THR3) modulate_kernel(
    const float* __restrict__ x, const int* __restrict__ idx,
    float* __restrict__ out, int N)
{
    __shared__ float4 s_gate[NUM_SEG * 32];  // 8KB

    for (int i = threadIdx.x; i < NUM_SEG * 32; i += THR3)
        s_gate[i] = ((const float4*)g_gate)[i];
    __syncthreads();

    const float4* X = (const float4*)x;
    float4* O = (float4*)out;
    const int total  = N * 32;
    const int stride = NBLK3 * THR3;

    #pragma unroll 4
    for (int i = blockIdx.x * THR3 + threadIdx.x; i < total; i += stride) {
        int row  = i >> 5;
        int lane = i & 31;
        int s = __ldg(idx + row);
        float4 v = __ldcs(X + i);
        float4 g = s_gate[s * 32 + lane];
        unsigned long long* vp = (unsigned long long*)&v;
        const unsigned long long* gp = (const unsigned long long*)&g;
        vp[0] = fmul2(vp[0], gp[0]);
        vp[1] = fmul2(vp[1], gp[1]);
        __stcs(O + i, v);
    }
}

// ---------------------------------------------------------------------------
extern "C" void kernel_launch(void* const* d_in, const int* in_sizes, int n_in,
                              void* d_out, int out_size)
{
    const float* x   = (const float*)d_in[0];
    const int*   idx = (const int*)d_in[1];
    const float* W1  = (const float*)d_in[2];
    const float* W2  = (const float*)d_in[3];
    float* out = (float*)d_out;

    const int N = in_sizes[1];  // number of points

    seg_sum_kernel<<<NBLK1, THR1>>>(x, idx, N);
    reduce_mlp_kernel<<<NUM_SEG, CHAN>>>(W1, W2);
    modulate_kernel<<<NBLK3, THR3>>>(x, idx, out, N);
}